// round 6
// baseline (speedup 1.0000x reference)
#include <cuda_runtime.h>
#include <cuda_bf16.h>
#include <cstdint>

#define U_N 4096
#define I_N 8192
#define ROWS_T 12288

// ---------------- static device scratch (no runtime allocation) ----------------
__device__ __align__(256) uint32_t g_bitsUI[(size_t)U_N * 256]; // [u][i/32]
__device__ __align__(256) uint32_t g_bitsIU[(size_t)I_N * 128]; // [i][u/32]
__device__ float g_ru[U_N];
__device__ float g_ri[I_N];
// GEMM B operands, layout [n][k]: n<64 = hi of dim n, n>=64 = lo of dim n-64
__device__ __align__(256) __nv_bfloat16 g_B1[(size_t)128 * U_N]; // k = user
__device__ __align__(256) __nv_bfloat16 g_B2[(size_t)128 * I_N]; // k = item
__device__ __align__(256) float g_raw1[(size_t)I_N * 128];
__device__ __align__(256) float g_raw2[(size_t)2 * U_N * 128];   // 2 K-splits
__device__ __align__(256) float g_x[(size_t)ROWS_T * 64];
__device__ __align__(256) float g_acc[(size_t)ROWS_T * 64];

// ---------------- P1: pack adjacency bits (both orientations) ----------------
__global__ __launch_bounds__(256) void pack_kernel(const int* __restrict__ edge) {
    int gw   = (blockIdx.x * 256 + threadIdx.x) >> 5;  // 32768 warps: 128 u-tiles x 256 i-tiles
    int lane = threadIdx.x & 31;
    int tu = gw >> 8;
    int ti = gw & 255;
    const int* base = edge + (size_t)tu * 32 * 8192 + ti * 32 + lane;
    uint32_t my = 0, uiw = 0;
    #pragma unroll 4
    for (int r = 0; r < 32; r++) {
        int val = base[(size_t)r * 8192];
        unsigned m = __ballot_sync(0xffffffffu, val != 0);
        my |= (uint32_t)(val != 0) << r;
        if (lane == r) uiw = m;
    }
    g_bitsUI[(size_t)(tu * 32 + lane) * 256 + ti] = uiw;
    g_bitsIU[(size_t)(ti * 32 + lane) * 128 + tu] = my;
}

// ---------------- P2: degrees -> rsqrt scales ----------------
__global__ __launch_bounds__(256) void scales_kernel() {
    int gw   = (blockIdx.x * 256 + threadIdx.x) >> 5;  // 12288 warps
    int lane = threadIdx.x & 31;
    int s = 0;
    if (gw < U_N) {
        const uint32_t* w = g_bitsUI + (size_t)gw * 256;
        for (int j = lane; j < 256; j += 32) s += __popc(w[j]);
        for (int o = 16; o; o >>= 1) s += __shfl_down_sync(0xffffffffu, s, o);
        if (!lane) g_ru[gw] = s ? rsqrtf((float)s) : 0.f;
    } else {
        int i = gw - U_N;
        const uint32_t* w = g_bitsIU + (size_t)i * 128;
        for (int j = lane; j < 128; j += 32) s += __popc(w[j]);
        for (int o = 16; o; o >>= 1) s += __shfl_down_sync(0xffffffffu, s, o);
        if (!lane) g_ri[i] = s ? rsqrtf((float)s) : 0.f;
    }
}

// ---------------- P3: per-layer operand prep (scale + hi/lo bf16 split, transpose) --
__global__ __launch_bounds__(256) void prep_kernel(const float* __restrict__ xin, int layer) {
    __shared__ float xs[64][65];
    int b = blockIdx.x, tid = threadIdx.x;
    const float* src = (layer == 0) ? xin : g_x;
    int k0, srow, K;
    const float* sc;
    __nv_bfloat16* dst;
    if (b < 64) { k0 = b * 64;        srow = k0;         sc = g_ru; dst = g_B1; K = U_N; }
    else        { k0 = (b - 64) * 64; srow = U_N + k0;   sc = g_ri; dst = g_B2; K = I_N; }
    for (int i = tid; i < 4096; i += 256)
        xs[i >> 6][i & 63] = src[(size_t)(srow + (i >> 6)) * 64 + (i & 63)];
    __syncthreads();
    int ul = tid & 63, db = tid >> 6;
    float s = sc[k0 + ul];
    #pragma unroll
    for (int j = 0; j < 16; j++) {
        int d = db + j * 4;
        float v = s * xs[ul][d];
        __nv_bfloat16 hi = __float2bfloat16(v);
        __nv_bfloat16 lo = __float2bfloat16(v - __bfloat162float(hi));
        dst[(size_t)d * K + k0 + ul] = hi;
        dst[(size_t)(d + 64) * K + k0 + ul] = lo;
    }
}

// ---------------- GEMM: bit-matrix x bf16, fp32 accum via mma.sync ----------------
__device__ __forceinline__ uint32_t pack2(uint32_t w) {
    return ((w & 1u) ? 0x3F80u : 0u) | ((w & 2u) ? 0x3F800000u : 0u);
}
__device__ __forceinline__ void mma16816(float* c, uint32_t a0, uint32_t a1, uint32_t a2,
                                         uint32_t a3, uint32_t b0, uint32_t b1) {
    asm volatile(
        "mma.sync.aligned.m16n8k16.row.col.f32.bf16.bf16.f32 "
        "{%0,%1,%2,%3}, {%4,%5,%6,%7}, {%8,%9}, {%0,%1,%2,%3};"
        : "+f"(c[0]), "+f"(c[1]), "+f"(c[2]), "+f"(c[3])
        : "r"(a0), "r"(a1), "r"(a2), "r"(a3), "r"(b0), "r"(b1));
}

__global__ __launch_bounds__(256) void gemm_kernel() {
    __shared__ __nv_bfloat16 Bs[128][72];  // [n][k], pad 72 for bank-conflict-free frags
    int b = blockIdx.x, tid = threadIdx.x;
    const uint32_t* bits;
    const __nv_bfloat16* Bg;
    float* raw;
    int m0, wpr, K, kbeg;
    if (b < 64) {            // dir1: top = A^T side, M=8192, K=4096
        bits = g_bitsIU; Bg = g_B1; raw = g_raw1;
        m0 = b * 128; wpr = 128; K = U_N; kbeg = 0;
    } else {                 // dir2: bot = A side, M=4096, K=8192, split-K=2
        int bb = b - 64, split = bb >> 5, mb = bb & 31;
        bits = g_bitsUI; Bg = g_B2; raw = g_raw2 + (size_t)split * U_N * 128;
        m0 = mb * 128; wpr = 256; K = I_N; kbeg = split * 4096;
    }
    int warp = tid >> 5, lane = tid & 31, g = lane >> 2, tig = lane & 3;
    int wm = warp >> 1, wn = warp & 1;
    int mw = m0 + wm * 32;
    int nw = wn * 64;
    float c[2][8][4];
    #pragma unroll
    for (int mt = 0; mt < 2; mt++)
        #pragma unroll
        for (int tn = 0; tn < 8; tn++)
            #pragma unroll
            for (int q = 0; q < 4; q++) c[mt][tn][q] = 0.f;

    for (int ch = 0; ch < 64; ch++) {      // 64 chunks of K=64 for every block
        int kg = kbeg + ch * 64;
        uint32_t wv[4][2];                 // bit words for this thread's 4 rows
        #pragma unroll
        for (int rid = 0; rid < 4; rid++) {
            int r = mw + g + rid * 8;
            uint2 t2 = *(const uint2*)(bits + (size_t)r * wpr + (kg >> 5));
            wv[rid][0] = t2.x; wv[rid][1] = t2.y;
        }
        __syncthreads();
        #pragma unroll
        for (int i = 0; i < 4; i++) {      // stage B chunk [128 n][64 k] = 1024 uint4
            int idx = tid + i * 256;
            int n = idx >> 3, k8 = idx & 7;
            *(uint4*)(&Bs[n][k8 * 8]) = *(const uint4*)(Bg + (size_t)n * K + kg + k8 * 8);
        }
        __syncthreads();
        #pragma unroll
        for (int s = 0; s < 4; s++) {      // 4 x K16 steps
            uint32_t bb_[8][2];
            #pragma unroll
            for (int tn = 0; tn < 8; tn++) {
                int n = nw + tn * 8 + g;
                bb_[tn][0] = *(const uint32_t*)(&Bs[n][s * 16 + 2 * tig]);
                bb_[tn][1] = *(const uint32_t*)(&Bs[n][s * 16 + 2 * tig + 8]);
            }
            int sh = (s & 1) * 16 + 2 * tig;
            #pragma unroll
            for (int mt = 0; mt < 2; mt++) {
                uint32_t wr  = wv[2 * mt][s >> 1] >> sh;
                uint32_t wr8 = wv[2 * mt + 1][s >> 1] >> sh;
                uint32_t a0 = pack2(wr), a1 = pack2(wr8);
                uint32_t a2 = pack2(wr >> 8), a3 = pack2(wr8 >> 8);
                #pragma unroll
                for (int tn = 0; tn < 8; tn++)
                    mma16816(c[mt][tn], a0, a1, a2, a3, bb_[tn][0], bb_[tn][1]);
            }
        }
    }
    #pragma unroll
    for (int mt = 0; mt < 2; mt++)
        #pragma unroll
        for (int tn = 0; tn < 8; tn++) {
            int row = mw + mt * 16 + g;
            int col = nw + tn * 8 + 2 * tig;
            float* p = raw + (size_t)row * 128 + col;
            p[0] = c[mt][tn][0]; p[1] = c[mt][tn][1];
            p += 8 * 128;
            p[0] = c[mt][tn][2]; p[1] = c[mt][tn][3];
        }
}

// ---------------- combine: hi+lo, split-K sum, degree scale, concat, accumulate ----
__global__ __launch_bounds__(256) void combine_kernel(float* out, int layer) {
    int idx = blockIdx.x * 256 + threadIdx.x;  // 786432 elems
    int row = idx >> 6, d = idx & 63;
    float v;
    if (row < I_N) {
        const float* p = g_raw1 + (size_t)row * 128 + d;
        v = g_ri[row] * (p[0] + p[64]);
    } else {
        int u = row - I_N;
        const float* p = g_raw2 + (size_t)u * 128 + d;
        const float* q = p + (size_t)U_N * 128;
        v = g_ru[u] * (p[0] + p[64] + q[0] + q[64]);
    }
    g_x[idx] = v;
    float a = (layer == 0) ? v : (g_acc[idx] + v);
    g_acc[idx] = a;
    if (out) out[idx] = a * 0.25f;
}

// ---------------- launch ----------------
extern "C" void kernel_launch(void* const* d_in, const int* in_sizes, int n_in,
                              void* d_out, int out_size) {
    const float* x    = (const float*)d_in[0];
    const int*   edge = (const int*)d_in[1];
    float*       out  = (float*)d_out;
    pack_kernel<<<4096, 256>>>(edge);
    scales_kernel<<<1536, 256>>>();
    for (int l = 0; l < 3; l++) {
        prep_kernel<<<192, 256>>>(x, l);
        gemm_kernel<<<128, 256>>>();
        combine_kernel<<<3072, 256>>>(l == 2 ? out : nullptr, l);
    }
}